// round 16
// baseline (speedup 1.0000x reference)
#include <cuda_runtime.h>
#include <cuda_bf16.h>
#include <cuda_fp16.h>
#include <cstdint>
#include <math.h>

#define D_MODEL 1024
#define D_STATE 16
#define D_INNER 2048
#define DT_RANK 64
#define BATCH   4
#define SEQLEN  2048
#define ROWS    (BATCH * SEQLEN)   // 8192

// ---------------- device scratch (allocation-free rule) -----------------------
__device__ __align__(16) float g_delta[ROWS * D_INNER];   // fp32 (exp-amplified)
__device__ __align__(16) float g_Bm[ROWS * D_STATE];
__device__ __align__(16) float g_Cm[ROWS * D_STATE];

// fp16 operands / intermediates
__device__ __align__(16) __half g_x16  [ROWS * D_MODEL];             // G1 A
__device__ __align__(16) __half g_Win16[(2 * D_INNER) * D_MODEL];    // G1 B
__device__ __align__(16) __half g_u16  [ROWS * D_INNER];             // G1u out
__device__ __align__(16) __half g_z16  [ROWS * D_INNER];             // G1z out
__device__ __align__(16) __half g_uc16 [ROWS * D_INNER];             // conv out
__device__ __align__(16) __half g_Wxp16[128 * D_INNER];              // G2 B (hi)
__device__ __align__(16) __half g_dtr16[ROWS * 2 * DT_RANK];         // G2 epi out [hi|lo]
__device__ __align__(16) __half g_Wdt16[D_INNER * 2 * DT_RANK];      // G3 B [hi|hi]
__device__ __align__(16) __half g_y16  [ROWS * D_INNER];             // scan out
__device__ __align__(16) __half g_Wout16[D_MODEL * D_INNER];         // G5 B

// ---------------- helpers -----------------------------------------------------
__device__ __forceinline__ uint32_t smem_u32(const void* p) {
    uint32_t a;
    asm("{ .reg .u64 t; cvta.to.shared.u64 t, %1; cvt.u32.u64 %0, t; }" : "=r"(a) : "l"(p));
    return a;
}
__device__ __forceinline__ void cp16(uint32_t saddr, const void* gaddr) {
    asm volatile("cp.async.cg.shared.global [%0], [%1], 16;" :: "r"(saddr), "l"(gaddr));
}
#define SWZ(o) ((o) ^ ((((uint32_t)(o)) >> 3) & 0x70))

__device__ __forceinline__ void ldm_x4(uint32_t& r0, uint32_t& r1, uint32_t& r2, uint32_t& r3,
                                       uint32_t addr) {
    asm volatile("ldmatrix.sync.aligned.m8n8.x4.shared.b16 {%0,%1,%2,%3}, [%4];"
                 : "=r"(r0), "=r"(r1), "=r"(r2), "=r"(r3) : "r"(addr));
}
__device__ __forceinline__ void mma_fp16(float& c0, float& c1, float& c2, float& c3,
                                         uint32_t a0, uint32_t a1, uint32_t a2, uint32_t a3,
                                         uint32_t b0, uint32_t b1) {
    asm volatile("mma.sync.aligned.m16n8k16.row.col.f32.f16.f16.f32 "
                 "{%0,%1,%2,%3}, {%4,%5,%6,%7}, {%8,%9}, {%0,%1,%2,%3};"
                 : "+f"(c0), "+f"(c1), "+f"(c2), "+f"(c3)
                 : "r"(a0), "r"(a1), "r"(a2), "r"(a3), "r"(b0), "r"(b1));
}
__device__ __forceinline__ void split_fp16(float v, __half& h, __half& l) {
    h = __float2half(v);
    l = __float2half(v - __half2float(h));
}

// ---------------- mma.sync fp16 GEMM (strided operands) ------------------------
// C[M,N] = A[M,Kp] * Bt[N,Kp]^T with row strides lda/ldb (elements), fp32 accum.
// BM = WM*64, BN=128, BK=64 (128B rows, xor-swizzled), 3-stage cp.async pipeline,
// 256 threads = 8 warps in 4(m) x 2(n), warp tile (WM*16) x 64.
enum { EPI_PLAIN = 0, EPI_PLAIN16 = 1, EPI_SOFTPLUS = 2, EPI_XPROJ = 3 };

#define GBN 128
#define GBK 64
#define GSTAGES 3
#define GTILEB_B (GBN * GBK * 2)                 // 16384 bytes (B tile)
#define GEMM_SMEM_WM(WM) (GSTAGES * ((WM) * 64 * GBK * 2 + GTILEB_B))
// WM=2: 98304, WM=1: 73728

template <int EPI, int WM>
__global__ __launch_bounds__(256, 2)
void gemm_tc(const uint8_t* __restrict__ A, const uint8_t* __restrict__ Bt,
             int lda, int ldb, int Kp, int N,
             float* __restrict__ O0, float* __restrict__ O1,
             __half* __restrict__ H0,
             const float* __restrict__ bias)
{
    constexpr int BM = WM * 64;
    constexpr int GTILEA_B = BM * GBK * 2;
    constexpr int GSTAGE_B = GTILEA_B + GTILEB_B;

    extern __shared__ char smem[];
    const uint32_t sb = smem_u32(smem);
    const int tid = threadIdx.x;
    const int wid = tid >> 5, lid = tid & 31;
    const int wr = wid & 3;
    const int wc = wid >> 2;
    const int m0 = blockIdx.y * BM;
    const int n0 = blockIdx.x * GBN;
    const int chunks = Kp / GBK;

    const uint8_t* Ap = A + (size_t)m0 * lda * 2;
    const uint8_t* Bp = Bt + (size_t)n0 * ldb * 2;

    const int ldrow = tid >> 3;
    const int ldch  = tid & 7;

    auto load_stage = [&](int c) {
        const int s = c % GSTAGES;
        const uint32_t sa = sb + s * GSTAGE_B;
        const uint32_t sB = sa + GTILEA_B;
        const size_t k0b = (size_t)c * GBK * 2;
        #pragma unroll
        for (int j = 0; j < BM / 32; ++j) {
            const int r = ldrow + j * 32;
            const uint32_t so = SWZ(r * 128 + ldch * 16);
            cp16(sa + so, Ap + (size_t)r * lda * 2 + k0b + ldch * 16);
        }
        #pragma unroll
        for (int j = 0; j < 4; ++j) {
            const int r = ldrow + j * 32;
            const uint32_t so = SWZ(r * 128 + ldch * 16);
            cp16(sB + so, Bp + (size_t)r * ldb * 2 + k0b + ldch * 16);
        }
        asm volatile("cp.async.commit_group;" ::: "memory");
    };

    const int pre = (chunks < GSTAGES - 1) ? chunks : (GSTAGES - 1);
    for (int c = 0; c < pre; ++c) load_stage(c);

    float acc[WM][8][4];
    #pragma unroll
    for (int i = 0; i < WM; ++i)
        #pragma unroll
        for (int j = 0; j < 8; ++j)
            #pragma unroll
            for (int k = 0; k < 4; ++k) acc[i][j][k] = 0.f;

    const int lrow = lid & 15;
    const int lhalf = lid >> 4;

    for (int c = 0; c < chunks; ++c) {
        const int remaining = chunks - 1 - c;
        if (remaining >= 1) asm volatile("cp.async.wait_group 1;" ::: "memory");
        else                asm volatile("cp.async.wait_group 0;" ::: "memory");
        __syncthreads();

        if (c + GSTAGES - 1 < chunks) load_stage(c + GSTAGES - 1);

        const int s = c % GSTAGES;
        const uint32_t sa = sb + s * GSTAGE_B;
        const uint32_t sB = sa + GTILEA_B;

        #pragma unroll
        for (int kk = 0; kk < 4; ++kk) {
            uint32_t a[WM][4];
            #pragma unroll
            for (int wm = 0; wm < WM; ++wm) {
                const int row = wr * (WM * 16) + wm * 16 + lrow;
                const uint32_t off = SWZ(row * 128 + (kk * 2 + lhalf) * 16);
                ldm_x4(a[wm][0], a[wm][1], a[wm][2], a[wm][3], sa + off);
            }
            uint32_t b[4][4];
            #pragma unroll
            for (int g = 0; g < 4; ++g) {
                const int row = wc * 64 + g * 16 + lrow;
                const uint32_t off = SWZ(row * 128 + (kk * 2 + lhalf) * 16);
                ldm_x4(b[g][0], b[g][1], b[g][2], b[g][3], sB + off);
            }
            #pragma unroll
            for (int wm = 0; wm < WM; ++wm)
                #pragma unroll
                for (int j = 0; j < 8; ++j) {
                    const int g = j >> 1, h = j & 1;
                    mma_fp16(acc[wm][j][0], acc[wm][j][1], acc[wm][j][2], acc[wm][j][3],
                             a[wm][0], a[wm][1], a[wm][2], a[wm][3],
                             b[g][h], b[g][2 + h]);
                }
        }
    }

    // ---------------- epilogue ------------------------------------------------
    const int tq = lid >> 2;
    const int tr = lid & 3;
    #pragma unroll
    for (int wm = 0; wm < WM; ++wm) {
        #pragma unroll
        for (int j = 0; j < 8; ++j) {
            #pragma unroll
            for (int half = 0; half < 2; ++half) {
                const int gr = m0 + wr * (WM * 16) + wm * 16 + tq + half * 8;
                const int gc = n0 + wc * 64 + j * 8 + tr * 2;
                float v0 = acc[wm][j][half * 2 + 0];
                float v1 = acc[wm][j][half * 2 + 1];
                if (EPI == EPI_PLAIN) {
                    float2 v = {v0, v1};
                    *(float2*)&O0[(size_t)gr * N + gc] = v;
                } else if (EPI == EPI_PLAIN16) {
                    __half2 v; v.x = __float2half(v0); v.y = __float2half(v1);
                    *(__half2*)&H0[(size_t)gr * N + gc] = v;
                } else if (EPI == EPI_SOFTPLUS) {
                    v0 += bias[gc]; v1 += bias[gc + 1];
                    v0 = (v0 > 20.0f) ? v0 : log1pf(__expf(v0));
                    v1 = (v1 > 20.0f) ? v1 : log1pf(__expf(v1));
                    float2 v = {v0, v1};
                    *(float2*)&O0[(size_t)gr * N + gc] = v;
                } else {
                    // EPI_XPROJ: 0..63 -> dtr16 fp16 [hi|lo] | 64..79 Bm | 80..95 Cm
                    if (gc < DT_RANK) {
                        __half h0, l0, h1, l1;
                        split_fp16(v0, h0, l0);
                        split_fp16(v1, h1, l1);
                        __half2 hh; hh.x = h0; hh.y = h1;
                        __half2 ll; ll.x = l0; ll.y = l1;
                        __half* q = H0 + (size_t)gr * 2 * DT_RANK + gc;
                        *(__half2*)(q)           = hh;
                        *(__half2*)(q + DT_RANK) = ll;
                    } else if (gc < DT_RANK + 16) {
                        float2 v = {v0, v1};
                        *(float2*)&O0[(size_t)gr * 16 + (gc - DT_RANK)] = v;
                    } else if (gc < DT_RANK + 32) {
                        float2 v = {v0, v1};
                        *(float2*)&O1[(size_t)gr * 16 + (gc - DT_RANK - 16)] = v;
                    }
                }
            }
        }
    }
}

// ---------------- packing kernels ---------------------------------------------
// fp16 1-term Bt: fp32[K, ldn] cols [ncol0, ncol0+Nv) -> fp16[Np, K] (plain hi)
__global__ __launch_bounds__(256)
void packBt16_1t_kernel(const float* __restrict__ in, __half* __restrict__ out,
                        int K, int Nv, int Np, int ldn, int ncol0)
{
    __shared__ float s[32][33];
    const int kb = blockIdx.x * 32, nb = blockIdx.y * 32;
    const int tx = threadIdx.x & 31, ty = threadIdx.x >> 5;
    #pragma unroll
    for (int r = 0; r < 32; r += 8) {
        const int k = kb + ty + r, n = nb + tx;
        s[ty + r][tx] = (k < K && n < Nv) ? in[(size_t)k * ldn + ncol0 + n] : 0.0f;
    }
    __syncthreads();
    #pragma unroll
    for (int r = 0; r < 32; r += 8) {
        const int n = nb + ty + r, k = kb + tx;
        if (n < Np && k < K)
            out[(size_t)n * K + k] = __float2half(s[tx][ty + r]);
    }
}

// fp16 dup Bt: fp32[K, ldn] cols [ncol0, ncol0+Nv) -> fp16[Np, 2K] = [hi|hi]
__global__ __launch_bounds__(256)
void packBt16_dup_kernel(const float* __restrict__ in, __half* __restrict__ out,
                         int K, int Nv, int Np, int ldn, int ncol0)
{
    __shared__ float s[32][33];
    const int kb = blockIdx.x * 32, nb = blockIdx.y * 32;
    const int tx = threadIdx.x & 31, ty = threadIdx.x >> 5;
    #pragma unroll
    for (int r = 0; r < 32; r += 8) {
        const int k = kb + ty + r, n = nb + tx;
        s[ty + r][tx] = (k < K && n < Nv) ? in[(size_t)k * ldn + ncol0 + n] : 0.0f;
    }
    __syncthreads();
    #pragma unroll
    for (int r = 0; r < 32; r += 8) {
        const int n = nb + ty + r, k = kb + tx;
        if (n < Np && k < K) {
            const __half h = __float2half(s[tx][ty + r]);
            __half* op = out + (size_t)n * 2 * K;
            op[k] = h; op[K + k] = h;
        }
    }
}

// fp16 1-term A: fp32 -> fp16 elementwise (flat, float4/thread)
__global__ __launch_bounds__(256)
void packA16_1t_kernel(const float* __restrict__ in, __half* __restrict__ out,
                       int total4)
{
    const int idx = blockIdx.x * 256 + threadIdx.x;
    if (idx >= total4) return;
    const float4 v = *(const float4*)(in + (size_t)idx * 4);
    __half2 a, b;
    a.x = __float2half(v.x); a.y = __float2half(v.y);
    b.x = __float2half(v.z); b.y = __float2half(v.w);
    *(__half2*)(out + (size_t)idx * 4)     = a;
    *(__half2*)(out + (size_t)idx * 4 + 2) = b;
}

// ---------------- causal depthwise conv (k=4) + SiLU (fp16 in/out) ------------
__global__ __launch_bounds__(256)
void conv_silu_kernel(const __half* __restrict__ u16, const float* __restrict__ w,
                      const float* __restrict__ bias, __half* __restrict__ uc16)
{
    constexpr int CHUNK = 16;
    int gid = blockIdx.x * blockDim.x + threadIdx.x;
    int d = gid & (D_INNER - 1);
    int rest = gid >> 11;
    int b = rest & (BATCH - 1);
    int chunk = rest >> 2;
    int l0 = chunk * CHUNK;

    const float w0 = w[d * 4 + 0], w1 = w[d * 4 + 1],
                w2 = w[d * 4 + 2], w3 = w[d * 4 + 3];
    const float bb = bias[d];

    const size_t base = ((size_t)b * SEQLEN + l0) * D_INNER + d;
    const __half* up = u16 + base;
    __half* op = uc16 + base;

    float xm3, xm2, xm1;
    if (l0 == 0) { xm3 = 0.f; xm2 = 0.f; xm1 = 0.f; }
    else {
        xm3 = __half2float(up[-3 * D_INNER]);
        xm2 = __half2float(up[-2 * D_INNER]);
        xm1 = __half2float(up[-1 * D_INNER]);
    }
    #pragma unroll
    for (int i = 0; i < CHUNK; ++i) {
        float cur = __half2float(up[(size_t)i * D_INNER]);
        float v = fmaf(xm3, w0, fmaf(xm2, w1, fmaf(xm1, w2, fmaf(cur, w3, bb))));
        float s = v / (1.0f + __expf(-v));
        op[(size_t)i * D_INNER] = __float2half(s);
        xm3 = xm2; xm2 = xm1; xm1 = cur;
    }
}

// ---------------- selective scan: 8 threads per (b,d) channel -----------------
// 2 states per thread, 3-level shfl reduction, software-pipelined loads.
__global__ __launch_bounds__(128)
void scan_kernel(const float* __restrict__ delta, const __half* __restrict__ uc16,
                 const __half* __restrict__ z16, const float* __restrict__ Bm,
                 const float* __restrict__ Cm, const float* __restrict__ A_log,
                 const float* __restrict__ Dp, __half* __restrict__ y16)
{
    const int t = blockIdx.x * blockDim.x + threadIdx.x;   // 65536 threads
    const int sub = t & 7;
    const int ch = t >> 3;
    const int d = ch & (D_INNER - 1);
    const int b = ch >> 11;
    const int n0 = sub * 2;

    const float a0 = -__expf(A_log[d * D_STATE + n0 + 0]);
    const float a1 = -__expf(A_log[d * D_STATE + n0 + 1]);

    const bool fast =
        fabsf(a0 + (float)(n0 + 1)) < 1e-3f * (n0 + 1) &&
        fabsf(a1 + (float)(n0 + 2)) < 1e-3f * (n0 + 2);

    const size_t base = (size_t)b * SEQLEN * D_INNER + d;
    const float* dp = delta + base;
    const __half* up = uc16 + base;
    const __half* zp = z16 + base;
    __half* yp = y16 + base;
    const float2* Bp = (const float2*)Bm + (size_t)b * SEQLEN * 8 + sub;
    const float2* Cp = (const float2*)Cm + (size_t)b * SEQLEN * 8 + sub;
    const float Dd = Dp[d];

    float h0 = 0.f, h1 = 0.f;

    float dt = dp[0];
    float uu = __half2float(up[0]);
    float2 Bv = Bp[0];
    float2 Cv = Cp[0];

    if (fast) {
        #pragma unroll 2
        for (int l = 0; l < SEQLEN; ++l) {
            const int ln = (l + 1 < SEQLEN) ? (l + 1) : (SEQLEN - 1);
            const float  dt_n = dp[(size_t)ln * D_INNER];
            const float  uu_n = __half2float(up[(size_t)ln * D_INNER]);
            const float2 Bv_n = Bp[(size_t)ln * 8];
            const float2 Cv_n = Cp[(size_t)ln * 8];

            const float e  = __expf(-dt);
            const float e2 = e * e;
            const float e4 = e2 * e2;
            const float e8 = e4 * e4;
            float m = 1.f;
            if (sub & 1) m = e2;
            if (sub & 2) m *= e4;
            if (sub & 4) m *= e8;
            const float dA0 = m * e;
            const float dA1 = dA0 * e;
            const float xv = dt * uu;
            h0 = fmaf(h0, dA0, xv * Bv.x);
            h1 = fmaf(h1, dA1, xv * Bv.y);
            float yv = h0 * Cv.x + h1 * Cv.y;
            yv += __shfl_xor_sync(0xffffffffu, yv, 1);
            yv += __shfl_xor_sync(0xffffffffu, yv, 2);
            yv += __shfl_xor_sync(0xffffffffu, yv, 4);
            if (sub == 0) {
                const float zz = __half2float(zp[(size_t)l * D_INNER]);
                const float sz = zz / (1.0f + __expf(-zz));
                yp[(size_t)l * D_INNER] = __float2half((yv + uu * Dd) * sz);
            }
            dt = dt_n; uu = uu_n; Bv = Bv_n; Cv = Cv_n;
        }
    } else {
        #pragma unroll 2
        for (int l = 0; l < SEQLEN; ++l) {
            const int ln = (l + 1 < SEQLEN) ? (l + 1) : (SEQLEN - 1);
            const float  dt_n = dp[(size_t)ln * D_INNER];
            const float  uu_n = __half2float(up[(size_t)ln * D_INNER]);
            const float2 Bv_n = Bp[(size_t)ln * 8];
            const float2 Cv_n = Cp[(size_t)ln * 8];

            const float dA0 = __expf(dt * a0);
            const float dA1 = __expf(dt * a1);
            const float xv = dt * uu;
            h0 = fmaf(h0, dA0, xv * Bv.x);
            h1 = fmaf(h1, dA1, xv * Bv.y);
            float yv = h0 * Cv.x + h1 * Cv.y;
            yv += __shfl_xor_sync(0xffffffffu, yv, 1);
            yv += __shfl_xor_sync(0xffffffffu, yv, 2);
            yv += __shfl_xor_sync(0xffffffffu, yv, 4);
            if (sub == 0) {
                const float zz = __half2float(zp[(size_t)l * D_INNER]);
                const float sz = zz / (1.0f + __expf(-zz));
                yp[(size_t)l * D_INNER] = __float2half((yv + uu * Dd) * sz);
            }
            dt = dt_n; uu = uu_n; Bv = Bv_n; Cv = Cv_n;
        }
    }
}

// ---------------- launch ------------------------------------------------------
extern "C" void kernel_launch(void* const* d_in, const int* in_sizes, int n_in,
                              void* d_out, int out_size)
{
    const float* x      = (const float*)d_in[0];
    const float* W_in   = (const float*)d_in[1];
    const float* conv_w = (const float*)d_in[2];
    const float* conv_b = (const float*)d_in[3];
    const float* W_xprj = (const float*)d_in[4];
    const float* W_dt   = (const float*)d_in[5];
    const float* b_dt   = (const float*)d_in[6];
    const float* A_log  = (const float*)d_in[7];
    const float* Dp     = (const float*)d_in[8];
    const float* W_out  = (const float*)d_in[9];
    float* out = (float*)d_out;

    float *delta, *Bm, *Cm;
    cudaGetSymbolAddress((void**)&delta, g_delta);
    cudaGetSymbolAddress((void**)&Bm,    g_Bm);
    cudaGetSymbolAddress((void**)&Cm,    g_Cm);

    __half *x16, *Win16, *u16, *z16, *uc16, *Wxp16, *dtr16, *Wdt16, *y16, *Wout16;
    cudaGetSymbolAddress((void**)&x16,    g_x16);
    cudaGetSymbolAddress((void**)&Win16,  g_Win16);
    cudaGetSymbolAddress((void**)&u16,    g_u16);
    cudaGetSymbolAddress((void**)&z16,    g_z16);
    cudaGetSymbolAddress((void**)&uc16,   g_uc16);
    cudaGetSymbolAddress((void**)&Wxp16,  g_Wxp16);
    cudaGetSymbolAddress((void**)&dtr16,  g_dtr16);
    cudaGetSymbolAddress((void**)&Wdt16,  g_Wdt16);
    cudaGetSymbolAddress((void**)&y16,    g_y16);
    cudaGetSymbolAddress((void**)&Wout16, g_Wout16);

    const int SM2 = GEMM_SMEM_WM(2);   // 98304
    const int SM1 = GEMM_SMEM_WM(1);   // 73728

    cudaFuncSetAttribute(gemm_tc<EPI_PLAIN16, 2>,  cudaFuncAttributeMaxDynamicSharedMemorySize, SM2);
    cudaFuncSetAttribute(gemm_tc<EPI_PLAIN, 1>,    cudaFuncAttributeMaxDynamicSharedMemorySize, SM1);
    cudaFuncSetAttribute(gemm_tc<EPI_SOFTPLUS, 1>, cudaFuncAttributeMaxDynamicSharedMemorySize, SM1);
    cudaFuncSetAttribute(gemm_tc<EPI_XPROJ, 1>,    cudaFuncAttributeMaxDynamicSharedMemorySize, SM1);

    // static side stream + fork/join events (created once, outside capture)
    static cudaStream_t s2 = nullptr;
    static cudaEvent_t evFork = nullptr, evJoin = nullptr;
    if (s2 == nullptr) {
        cudaStreamCreateWithFlags(&s2, cudaStreamNonBlocking);
        cudaEventCreateWithFlags(&evFork, cudaEventDisableTiming);
        cudaEventCreateWithFlags(&evJoin, cudaEventDisableTiming);
    }

    // weight packs (default stream)
    packBt16_1t_kernel<<<dim3(D_MODEL / 32, (2 * D_INNER) / 32), 256>>>(
        W_in, Win16, D_MODEL, 2 * D_INNER, 2 * D_INNER, 2 * D_INNER, 0);
    packBt16_1t_kernel<<<dim3(D_INNER / 32, 128 / 32), 256>>>(
        W_xprj, Wxp16, D_INNER, DT_RANK + 2 * D_STATE, 128, DT_RANK + 2 * D_STATE, 0);
    packBt16_dup_kernel<<<dim3((DT_RANK + 31) / 32, D_INNER / 32), 256>>>(
        W_dt, Wdt16, DT_RANK, D_INNER, D_INNER, D_INNER, 0);
    packBt16_1t_kernel<<<dim3(D_INNER / 32, D_MODEL / 32), 256>>>(
        W_out, Wout16, D_INNER, D_MODEL, D_MODEL, D_MODEL, 0);

    // activation pack for G1 (plain fp16 hi)
    packA16_1t_kernel<<<(ROWS * D_MODEL / 4 + 255) / 256, 256>>>(
        x, x16, ROWS * D_MODEL / 4);

    // ---- fork: G1z on side stream (z not needed until scan) ----------------
    cudaEventRecord(evFork, 0);
    cudaStreamWaitEvent(s2, evFork, 0);
    gemm_tc<EPI_PLAIN16, 2><<<dim3(D_INNER / GBN, ROWS / 128), 256, SM2, s2>>>(
        (const uint8_t*)x16, (const uint8_t*)(Win16 + (size_t)D_INNER * D_MODEL),
        D_MODEL, D_MODEL, D_MODEL, D_INNER,
        nullptr, nullptr, z16, nullptr);
    cudaEventRecord(evJoin, s2);

    // ---- main chain: G1u -> conv -> G2 -> G3 (default stream) --------------
    gemm_tc<EPI_PLAIN16, 2><<<dim3(D_INNER / GBN, ROWS / 128), 256, SM2>>>(
        (const uint8_t*)x16, (const uint8_t*)Win16,
        D_MODEL, D_MODEL, D_MODEL, D_INNER,
        nullptr, nullptr, u16, nullptr);

    conv_silu_kernel<<<(BATCH * D_INNER * (SEQLEN / 16)) / 256, 256>>>(
        u16, conv_w, conv_b, uc16);

    gemm_tc<EPI_XPROJ, 1><<<dim3(1, ROWS / 64), 256, SM1>>>(
        (const uint8_t*)uc16, (const uint8_t*)Wxp16,
        D_INNER, D_INNER, D_INNER, 128,
        Bm, Cm, dtr16, nullptr);

    gemm_tc<EPI_SOFTPLUS, 1><<<dim3(D_INNER / GBN, ROWS / 64), 256, SM1>>>(
        (const uint8_t*)dtr16, (const uint8_t*)Wdt16,
        2 * DT_RANK, 2 * DT_RANK, 2 * DT_RANK, D_INNER,
        delta, nullptr, nullptr, b_dt);

    // ---- join: scan needs z16 ----------------------------------------------
    cudaStreamWaitEvent(0, evJoin, 0);
    scan_kernel<<<(ROWS * 8) / 128, 128>>>(delta, uc16, z16, Bm, Cm, A_log, Dp, y16);

    // ---- G5: out = y @ W_out (fp16 1-term, BM=64) --------------------------
    gemm_tc<EPI_PLAIN, 1><<<dim3(D_MODEL / GBN, ROWS / 64), 256, SM1>>>(
        (const uint8_t*)y16, (const uint8_t*)Wout16,
        D_INNER, D_INNER, D_INNER, D_MODEL,
        out, nullptr, nullptr, nullptr);
}

// round 17
// speedup vs baseline: 1.0172x; 1.0172x over previous
#include <cuda_runtime.h>
#include <cuda_bf16.h>
#include <cuda_fp16.h>
#include <cstdint>
#include <math.h>

#define D_MODEL 1024
#define D_STATE 16
#define D_INNER 2048
#define DT_RANK 64
#define BATCH   4
#define SEQLEN  2048
#define ROWS    (BATCH * SEQLEN)   // 8192

// ---------------- device scratch (allocation-free rule) -----------------------
__device__ __align__(16) float g_delta[ROWS * D_INNER];   // fp32 (exp-amplified)
__device__ __align__(16) float g_Bm[ROWS * D_STATE];
__device__ __align__(16) float g_Cm[ROWS * D_STATE];

// fp16 operands / intermediates
__device__ __align__(16) __half g_x16  [ROWS * D_MODEL];             // G1 A
__device__ __align__(16) __half g_Win16[(2 * D_INNER) * D_MODEL];    // G1 B
__device__ __align__(16) __half g_u16  [ROWS * D_INNER];             // G1u out
__device__ __align__(16) __half g_z16  [ROWS * D_INNER];             // G1z out
__device__ __align__(16) __half g_uc16 [ROWS * D_INNER];             // conv out
__device__ __align__(16) __half g_Wxp16[128 * D_INNER];              // G2 B (hi)
__device__ __align__(16) __half g_dtr16[ROWS * 2 * DT_RANK];         // G2 epi out [hi|lo]
__device__ __align__(16) __half g_Wdt16[D_INNER * 2 * DT_RANK];      // G3 B [hi|hi]
__device__ __align__(16) __half g_y16  [ROWS * D_INNER];             // scan out
__device__ __align__(16) __half g_Wout16[D_MODEL * D_INNER];         // G5 B

// ---------------- helpers -----------------------------------------------------
__device__ __forceinline__ uint32_t smem_u32(const void* p) {
    uint32_t a;
    asm("{ .reg .u64 t; cvta.to.shared.u64 t, %1; cvt.u32.u64 %0, t; }" : "=r"(a) : "l"(p));
    return a;
}
__device__ __forceinline__ void cp16(uint32_t saddr, const void* gaddr) {
    asm volatile("cp.async.cg.shared.global [%0], [%1], 16;" :: "r"(saddr), "l"(gaddr));
}
#define SWZ(o) ((o) ^ ((((uint32_t)(o)) >> 3) & 0x70))

__device__ __forceinline__ void ldm_x4(uint32_t& r0, uint32_t& r1, uint32_t& r2, uint32_t& r3,
                                       uint32_t addr) {
    asm volatile("ldmatrix.sync.aligned.m8n8.x4.shared.b16 {%0,%1,%2,%3}, [%4];"
                 : "=r"(r0), "=r"(r1), "=r"(r2), "=r"(r3) : "r"(addr));
}
__device__ __forceinline__ void mma_fp16(float& c0, float& c1, float& c2, float& c3,
                                         uint32_t a0, uint32_t a1, uint32_t a2, uint32_t a3,
                                         uint32_t b0, uint32_t b1) {
    asm volatile("mma.sync.aligned.m16n8k16.row.col.f32.f16.f16.f32 "
                 "{%0,%1,%2,%3}, {%4,%5,%6,%7}, {%8,%9}, {%0,%1,%2,%3};"
                 : "+f"(c0), "+f"(c1), "+f"(c2), "+f"(c3)
                 : "r"(a0), "r"(a1), "r"(a2), "r"(a3), "r"(b0), "r"(b1));
}
__device__ __forceinline__ void split_fp16(float v, __half& h, __half& l) {
    h = __float2half(v);
    l = __float2half(v - __half2float(h));
}

// ---------------- mma.sync fp16 GEMM (strided operands) ------------------------
// C[M,N] = A[M,Kp] * Bt[N,Kp]^T with row strides lda/ldb (elements), fp32 accum.
// BM = WM*64, BN=128, BK=64 (128B rows, xor-swizzled), 3-stage cp.async pipeline,
// 256 threads = 8 warps in 4(m) x 2(n), warp tile (WM*16) x 64.
enum { EPI_PLAIN = 0, EPI_PLAIN16 = 1, EPI_SOFTPLUS = 2, EPI_XPROJ = 3 };

#define GBN 128
#define GBK 64
#define GSTAGES 3
#define GTILEB_B (GBN * GBK * 2)                 // 16384 bytes (B tile)
#define GEMM_SMEM_WM(WM) (GSTAGES * ((WM) * 64 * GBK * 2 + GTILEB_B))
// WM=2: 98304, WM=1: 73728

template <int EPI, int WM>
__global__ __launch_bounds__(256, 2)
void gemm_tc(const uint8_t* __restrict__ A, const uint8_t* __restrict__ Bt,
             int lda, int ldb, int Kp, int N,
             float* __restrict__ O0, float* __restrict__ O1,
             __half* __restrict__ H0,
             const float* __restrict__ bias)
{
    constexpr int BM = WM * 64;
    constexpr int GTILEA_B = BM * GBK * 2;
    constexpr int GSTAGE_B = GTILEA_B + GTILEB_B;

    extern __shared__ char smem[];
    const uint32_t sb = smem_u32(smem);
    const int tid = threadIdx.x;
    const int wid = tid >> 5, lid = tid & 31;
    const int wr = wid & 3;
    const int wc = wid >> 2;
    const int m0 = blockIdx.y * BM;
    const int n0 = blockIdx.x * GBN;
    const int chunks = Kp / GBK;

    const uint8_t* Ap = A + (size_t)m0 * lda * 2;
    const uint8_t* Bp = Bt + (size_t)n0 * ldb * 2;

    const int ldrow = tid >> 3;
    const int ldch  = tid & 7;

    auto load_stage = [&](int c) {
        const int s = c % GSTAGES;
        const uint32_t sa = sb + s * GSTAGE_B;
        const uint32_t sB = sa + GTILEA_B;
        const size_t k0b = (size_t)c * GBK * 2;
        #pragma unroll
        for (int j = 0; j < BM / 32; ++j) {
            const int r = ldrow + j * 32;
            const uint32_t so = SWZ(r * 128 + ldch * 16);
            cp16(sa + so, Ap + (size_t)r * lda * 2 + k0b + ldch * 16);
        }
        #pragma unroll
        for (int j = 0; j < 4; ++j) {
            const int r = ldrow + j * 32;
            const uint32_t so = SWZ(r * 128 + ldch * 16);
            cp16(sB + so, Bp + (size_t)r * ldb * 2 + k0b + ldch * 16);
        }
        asm volatile("cp.async.commit_group;" ::: "memory");
    };

    const int pre = (chunks < GSTAGES - 1) ? chunks : (GSTAGES - 1);
    for (int c = 0; c < pre; ++c) load_stage(c);

    float acc[WM][8][4];
    #pragma unroll
    for (int i = 0; i < WM; ++i)
        #pragma unroll
        for (int j = 0; j < 8; ++j)
            #pragma unroll
            for (int k = 0; k < 4; ++k) acc[i][j][k] = 0.f;

    const int lrow = lid & 15;
    const int lhalf = lid >> 4;

    for (int c = 0; c < chunks; ++c) {
        const int remaining = chunks - 1 - c;
        if (remaining >= 1) asm volatile("cp.async.wait_group 1;" ::: "memory");
        else                asm volatile("cp.async.wait_group 0;" ::: "memory");
        __syncthreads();

        if (c + GSTAGES - 1 < chunks) load_stage(c + GSTAGES - 1);

        const int s = c % GSTAGES;
        const uint32_t sa = sb + s * GSTAGE_B;
        const uint32_t sB = sa + GTILEA_B;

        #pragma unroll
        for (int kk = 0; kk < 4; ++kk) {
            uint32_t a[WM][4];
            #pragma unroll
            for (int wm = 0; wm < WM; ++wm) {
                const int row = wr * (WM * 16) + wm * 16 + lrow;
                const uint32_t off = SWZ(row * 128 + (kk * 2 + lhalf) * 16);
                ldm_x4(a[wm][0], a[wm][1], a[wm][2], a[wm][3], sa + off);
            }
            uint32_t b[4][4];
            #pragma unroll
            for (int g = 0; g < 4; ++g) {
                const int row = wc * 64 + g * 16 + lrow;
                const uint32_t off = SWZ(row * 128 + (kk * 2 + lhalf) * 16);
                ldm_x4(b[g][0], b[g][1], b[g][2], b[g][3], sB + off);
            }
            #pragma unroll
            for (int wm = 0; wm < WM; ++wm)
                #pragma unroll
                for (int j = 0; j < 8; ++j) {
                    const int g = j >> 1, h = j & 1;
                    mma_fp16(acc[wm][j][0], acc[wm][j][1], acc[wm][j][2], acc[wm][j][3],
                             a[wm][0], a[wm][1], a[wm][2], a[wm][3],
                             b[g][h], b[g][2 + h]);
                }
        }
    }

    // ---------------- epilogue ------------------------------------------------
    const int tq = lid >> 2;
    const int tr = lid & 3;
    #pragma unroll
    for (int wm = 0; wm < WM; ++wm) {
        #pragma unroll
        for (int j = 0; j < 8; ++j) {
            #pragma unroll
            for (int half = 0; half < 2; ++half) {
                const int gr = m0 + wr * (WM * 16) + wm * 16 + tq + half * 8;
                const int gc = n0 + wc * 64 + j * 8 + tr * 2;
                float v0 = acc[wm][j][half * 2 + 0];
                float v1 = acc[wm][j][half * 2 + 1];
                if (EPI == EPI_PLAIN) {
                    float2 v = {v0, v1};
                    *(float2*)&O0[(size_t)gr * N + gc] = v;
                } else if (EPI == EPI_PLAIN16) {
                    __half2 v; v.x = __float2half(v0); v.y = __float2half(v1);
                    *(__half2*)&H0[(size_t)gr * N + gc] = v;
                } else if (EPI == EPI_SOFTPLUS) {
                    v0 += bias[gc]; v1 += bias[gc + 1];
                    v0 = (v0 > 20.0f) ? v0 : log1pf(__expf(v0));
                    v1 = (v1 > 20.0f) ? v1 : log1pf(__expf(v1));
                    float2 v = {v0, v1};
                    *(float2*)&O0[(size_t)gr * N + gc] = v;
                } else {
                    // EPI_XPROJ: 0..63 -> dtr16 fp16 [hi|lo] | 64..79 Bm | 80..95 Cm
                    if (gc < DT_RANK) {
                        __half h0, l0, h1, l1;
                        split_fp16(v0, h0, l0);
                        split_fp16(v1, h1, l1);
                        __half2 hh; hh.x = h0; hh.y = h1;
                        __half2 ll; ll.x = l0; ll.y = l1;
                        __half* q = H0 + (size_t)gr * 2 * DT_RANK + gc;
                        *(__half2*)(q)           = hh;
                        *(__half2*)(q + DT_RANK) = ll;
                    } else if (gc < DT_RANK + 16) {
                        float2 v = {v0, v1};
                        *(float2*)&O0[(size_t)gr * 16 + (gc - DT_RANK)] = v;
                    } else if (gc < DT_RANK + 32) {
                        float2 v = {v0, v1};
                        *(float2*)&O1[(size_t)gr * 16 + (gc - DT_RANK - 16)] = v;
                    }
                }
            }
        }
    }
}

// ---------------- packing kernels ---------------------------------------------
// fp16 1-term Bt: fp32[K, ldn] cols [ncol0, ncol0+Nv) -> fp16[Np, K] (plain hi)
__global__ __launch_bounds__(256)
void packBt16_1t_kernel(const float* __restrict__ in, __half* __restrict__ out,
                        int K, int Nv, int Np, int ldn, int ncol0)
{
    __shared__ float s[32][33];
    const int kb = blockIdx.x * 32, nb = blockIdx.y * 32;
    const int tx = threadIdx.x & 31, ty = threadIdx.x >> 5;
    #pragma unroll
    for (int r = 0; r < 32; r += 8) {
        const int k = kb + ty + r, n = nb + tx;
        s[ty + r][tx] = (k < K && n < Nv) ? in[(size_t)k * ldn + ncol0 + n] : 0.0f;
    }
    __syncthreads();
    #pragma unroll
    for (int r = 0; r < 32; r += 8) {
        const int n = nb + ty + r, k = kb + tx;
        if (n < Np && k < K)
            out[(size_t)n * K + k] = __float2half(s[tx][ty + r]);
    }
}

// fp16 dup Bt: fp32[K, ldn] cols [ncol0, ncol0+Nv) -> fp16[Np, 2K] = [hi|hi]
__global__ __launch_bounds__(256)
void packBt16_dup_kernel(const float* __restrict__ in, __half* __restrict__ out,
                         int K, int Nv, int Np, int ldn, int ncol0)
{
    __shared__ float s[32][33];
    const int kb = blockIdx.x * 32, nb = blockIdx.y * 32;
    const int tx = threadIdx.x & 31, ty = threadIdx.x >> 5;
    #pragma unroll
    for (int r = 0; r < 32; r += 8) {
        const int k = kb + ty + r, n = nb + tx;
        s[ty + r][tx] = (k < K && n < Nv) ? in[(size_t)k * ldn + ncol0 + n] : 0.0f;
    }
    __syncthreads();
    #pragma unroll
    for (int r = 0; r < 32; r += 8) {
        const int n = nb + ty + r, k = kb + tx;
        if (n < Np && k < K) {
            const __half h = __float2half(s[tx][ty + r]);
            __half* op = out + (size_t)n * 2 * K;
            op[k] = h; op[K + k] = h;
        }
    }
}

// fp16 1-term A: fp32 -> fp16 elementwise (flat, float4/thread)
__global__ __launch_bounds__(256)
void packA16_1t_kernel(const float* __restrict__ in, __half* __restrict__ out,
                       int total4)
{
    const int idx = blockIdx.x * 256 + threadIdx.x;
    if (idx >= total4) return;
    const float4 v = *(const float4*)(in + (size_t)idx * 4);
    __half2 a, b;
    a.x = __float2half(v.x); a.y = __float2half(v.y);
    b.x = __float2half(v.z); b.y = __float2half(v.w);
    *(__half2*)(out + (size_t)idx * 4)     = a;
    *(__half2*)(out + (size_t)idx * 4 + 2) = b;
}

// ---------------- causal depthwise conv (k=4) + SiLU (fp16 in/out) ------------
__global__ __launch_bounds__(256)
void conv_silu_kernel(const __half* __restrict__ u16, const float* __restrict__ w,
                      const float* __restrict__ bias, __half* __restrict__ uc16)
{
    constexpr int CHUNK = 16;
    int gid = blockIdx.x * blockDim.x + threadIdx.x;
    int d = gid & (D_INNER - 1);
    int rest = gid >> 11;
    int b = rest & (BATCH - 1);
    int chunk = rest >> 2;
    int l0 = chunk * CHUNK;

    const float w0 = w[d * 4 + 0], w1 = w[d * 4 + 1],
                w2 = w[d * 4 + 2], w3 = w[d * 4 + 3];
    const float bb = bias[d];

    const size_t base = ((size_t)b * SEQLEN + l0) * D_INNER + d;
    const __half* up = u16 + base;
    __half* op = uc16 + base;

    float xm3, xm2, xm1;
    if (l0 == 0) { xm3 = 0.f; xm2 = 0.f; xm1 = 0.f; }
    else {
        xm3 = __half2float(up[-3 * D_INNER]);
        xm2 = __half2float(up[-2 * D_INNER]);
        xm1 = __half2float(up[-1 * D_INNER]);
    }
    #pragma unroll
    for (int i = 0; i < CHUNK; ++i) {
        float cur = __half2float(up[(size_t)i * D_INNER]);
        float v = fmaf(xm3, w0, fmaf(xm2, w1, fmaf(xm1, w2, fmaf(cur, w3, bb))));
        float s = v / (1.0f + __expf(-v));
        op[(size_t)i * D_INNER] = __float2half(s);
        xm3 = xm2; xm2 = xm1; xm1 = cur;
    }
}

// ---------------- selective scan: 8 threads per (b,d) channel -----------------
// 2 states per thread, 3-level shfl reduction, software-pipelined loads.
__global__ __launch_bounds__(128)
void scan_kernel(const float* __restrict__ delta, const __half* __restrict__ uc16,
                 const __half* __restrict__ z16, const float* __restrict__ Bm,
                 const float* __restrict__ Cm, const float* __restrict__ A_log,
                 const float* __restrict__ Dp, __half* __restrict__ y16)
{
    const int t = blockIdx.x * blockDim.x + threadIdx.x;   // 65536 threads
    const int sub = t & 7;
    const int ch = t >> 3;
    const int d = ch & (D_INNER - 1);
    const int b = ch >> 11;
    const int n0 = sub * 2;

    const float a0 = -__expf(A_log[d * D_STATE + n0 + 0]);
    const float a1 = -__expf(A_log[d * D_STATE + n0 + 1]);

    const bool fast =
        fabsf(a0 + (float)(n0 + 1)) < 1e-3f * (n0 + 1) &&
        fabsf(a1 + (float)(n0 + 2)) < 1e-3f * (n0 + 2);

    const size_t base = (size_t)b * SEQLEN * D_INNER + d;
    const float* dp = delta + base;
    const __half* up = uc16 + base;
    const __half* zp = z16 + base;
    __half* yp = y16 + base;
    const float2* Bp = (const float2*)Bm + (size_t)b * SEQLEN * 8 + sub;
    const float2* Cp = (const float2*)Cm + (size_t)b * SEQLEN * 8 + sub;
    const float Dd = Dp[d];

    float h0 = 0.f, h1 = 0.f;

    float dt = dp[0];
    float uu = __half2float(up[0]);
    float2 Bv = Bp[0];
    float2 Cv = Cp[0];

    if (fast) {
        #pragma unroll 2
        for (int l = 0; l < SEQLEN; ++l) {
            const int ln = (l + 1 < SEQLEN) ? (l + 1) : (SEQLEN - 1);
            const float  dt_n = dp[(size_t)ln * D_INNER];
            const float  uu_n = __half2float(up[(size_t)ln * D_INNER]);
            const float2 Bv_n = Bp[(size_t)ln * 8];
            const float2 Cv_n = Cp[(size_t)ln * 8];

            const float e  = __expf(-dt);
            const float e2 = e * e;
            const float e4 = e2 * e2;
            const float e8 = e4 * e4;
            float m = 1.f;
            if (sub & 1) m = e2;
            if (sub & 2) m *= e4;
            if (sub & 4) m *= e8;
            const float dA0 = m * e;
            const float dA1 = dA0 * e;
            const float xv = dt * uu;
            h0 = fmaf(h0, dA0, xv * Bv.x);
            h1 = fmaf(h1, dA1, xv * Bv.y);
            float yv = h0 * Cv.x + h1 * Cv.y;
            yv += __shfl_xor_sync(0xffffffffu, yv, 1);
            yv += __shfl_xor_sync(0xffffffffu, yv, 2);
            yv += __shfl_xor_sync(0xffffffffu, yv, 4);
            if (sub == 0) {
                const float zz = __half2float(zp[(size_t)l * D_INNER]);
                const float sz = zz / (1.0f + __expf(-zz));
                yp[(size_t)l * D_INNER] = __float2half((yv + uu * Dd) * sz);
            }
            dt = dt_n; uu = uu_n; Bv = Bv_n; Cv = Cv_n;
        }
    } else {
        #pragma unroll 2
        for (int l = 0; l < SEQLEN; ++l) {
            const int ln = (l + 1 < SEQLEN) ? (l + 1) : (SEQLEN - 1);
            const float  dt_n = dp[(size_t)ln * D_INNER];
            const float  uu_n = __half2float(up[(size_t)ln * D_INNER]);
            const float2 Bv_n = Bp[(size_t)ln * 8];
            const float2 Cv_n = Cp[(size_t)ln * 8];

            const float dA0 = __expf(dt * a0);
            const float dA1 = __expf(dt * a1);
            const float xv = dt * uu;
            h0 = fmaf(h0, dA0, xv * Bv.x);
            h1 = fmaf(h1, dA1, xv * Bv.y);
            float yv = h0 * Cv.x + h1 * Cv.y;
            yv += __shfl_xor_sync(0xffffffffu, yv, 1);
            yv += __shfl_xor_sync(0xffffffffu, yv, 2);
            yv += __shfl_xor_sync(0xffffffffu, yv, 4);
            if (sub == 0) {
                const float zz = __half2float(zp[(size_t)l * D_INNER]);
                const float sz = zz / (1.0f + __expf(-zz));
                yp[(size_t)l * D_INNER] = __float2half((yv + uu * Dd) * sz);
            }
            dt = dt_n; uu = uu_n; Bv = Bv_n; Cv = Cv_n;
        }
    }
}

// ---------------- launch ------------------------------------------------------
extern "C" void kernel_launch(void* const* d_in, const int* in_sizes, int n_in,
                              void* d_out, int out_size)
{
    const float* x      = (const float*)d_in[0];
    const float* W_in   = (const float*)d_in[1];
    const float* conv_w = (const float*)d_in[2];
    const float* conv_b = (const float*)d_in[3];
    const float* W_xprj = (const float*)d_in[4];
    const float* W_dt   = (const float*)d_in[5];
    const float* b_dt   = (const float*)d_in[6];
    const float* A_log  = (const float*)d_in[7];
    const float* Dp     = (const float*)d_in[8];
    const float* W_out  = (const float*)d_in[9];
    float* out = (float*)d_out;

    float *delta, *Bm, *Cm;
    cudaGetSymbolAddress((void**)&delta, g_delta);
    cudaGetSymbolAddress((void**)&Bm,    g_Bm);
    cudaGetSymbolAddress((void**)&Cm,    g_Cm);

    __half *x16, *Win16, *u16, *z16, *uc16, *Wxp16, *dtr16, *Wdt16, *y16, *Wout16;
    cudaGetSymbolAddress((void**)&x16,    g_x16);
    cudaGetSymbolAddress((void**)&Win16,  g_Win16);
    cudaGetSymbolAddress((void**)&u16,    g_u16);
    cudaGetSymbolAddress((void**)&z16,    g_z16);
    cudaGetSymbolAddress((void**)&uc16,   g_uc16);
    cudaGetSymbolAddress((void**)&Wxp16,  g_Wxp16);
    cudaGetSymbolAddress((void**)&dtr16,  g_dtr16);
    cudaGetSymbolAddress((void**)&Wdt16,  g_Wdt16);
    cudaGetSymbolAddress((void**)&y16,    g_y16);
    cudaGetSymbolAddress((void**)&Wout16, g_Wout16);

    const int SM2 = GEMM_SMEM_WM(2);   // 98304
    const int SM1 = GEMM_SMEM_WM(1);   // 73728

    cudaFuncSetAttribute(gemm_tc<EPI_PLAIN16, 2>,  cudaFuncAttributeMaxDynamicSharedMemorySize, SM2);
    cudaFuncSetAttribute(gemm_tc<EPI_PLAIN, 1>,    cudaFuncAttributeMaxDynamicSharedMemorySize, SM1);
    cudaFuncSetAttribute(gemm_tc<EPI_SOFTPLUS, 1>, cudaFuncAttributeMaxDynamicSharedMemorySize, SM1);
    cudaFuncSetAttribute(gemm_tc<EPI_XPROJ, 1>,    cudaFuncAttributeMaxDynamicSharedMemorySize, SM1);

    // static side stream + fork/join events (created once, outside capture)
    static cudaStream_t s2 = nullptr;
    static cudaEvent_t evFork = nullptr, evJoin = nullptr;
    if (s2 == nullptr) {
        cudaStreamCreateWithFlags(&s2, cudaStreamNonBlocking);
        cudaEventCreateWithFlags(&evFork, cudaEventDisableTiming);
        cudaEventCreateWithFlags(&evJoin, cudaEventDisableTiming);
    }

    // weight packs (default stream)
    packBt16_1t_kernel<<<dim3(D_MODEL / 32, (2 * D_INNER) / 32), 256>>>(
        W_in, Win16, D_MODEL, 2 * D_INNER, 2 * D_INNER, 2 * D_INNER, 0);
    packBt16_1t_kernel<<<dim3(D_INNER / 32, 128 / 32), 256>>>(
        W_xprj, Wxp16, D_INNER, DT_RANK + 2 * D_STATE, 128, DT_RANK + 2 * D_STATE, 0);
    packBt16_dup_kernel<<<dim3((DT_RANK + 31) / 32, D_INNER / 32), 256>>>(
        W_dt, Wdt16, DT_RANK, D_INNER, D_INNER, D_INNER, 0);
    packBt16_1t_kernel<<<dim3(D_INNER / 32, D_MODEL / 32), 256>>>(
        W_out, Wout16, D_INNER, D_MODEL, D_MODEL, D_MODEL, 0);

    // activation pack for G1 (plain fp16 hi)
    packA16_1t_kernel<<<(ROWS * D_MODEL / 4 + 255) / 256, 256>>>(
        x, x16, ROWS * D_MODEL / 4);

    // ---- fork: G1z on side stream (z not needed until scan) ----------------
    cudaEventRecord(evFork, 0);
    cudaStreamWaitEvent(s2, evFork, 0);
    gemm_tc<EPI_PLAIN16, 2><<<dim3(D_INNER / GBN, ROWS / 128), 256, SM2, s2>>>(
        (const uint8_t*)x16, (const uint8_t*)(Win16 + (size_t)D_INNER * D_MODEL),
        D_MODEL, D_MODEL, D_MODEL, D_INNER,
        nullptr, nullptr, z16, nullptr);
    cudaEventRecord(evJoin, s2);

    // ---- main chain: G1u -> conv -> G2 -> G3 (default stream) --------------
    gemm_tc<EPI_PLAIN16, 2><<<dim3(D_INNER / GBN, ROWS / 128), 256, SM2>>>(
        (const uint8_t*)x16, (const uint8_t*)Win16,
        D_MODEL, D_MODEL, D_MODEL, D_INNER,
        nullptr, nullptr, u16, nullptr);

    conv_silu_kernel<<<(BATCH * D_INNER * (SEQLEN / 16)) / 256, 256>>>(
        u16, conv_w, conv_b, uc16);

    gemm_tc<EPI_XPROJ, 1><<<dim3(1, ROWS / 64), 256, SM1>>>(
        (const uint8_t*)uc16, (const uint8_t*)Wxp16,
        D_INNER, D_INNER, D_INNER, 128,
        Bm, Cm, dtr16, nullptr);

    gemm_tc<EPI_SOFTPLUS, 1><<<dim3(D_INNER / GBN, ROWS / 64), 256, SM1>>>(
        (const uint8_t*)dtr16, (const uint8_t*)Wdt16,
        2 * DT_RANK, 2 * DT_RANK, 2 * DT_RANK, D_INNER,
        delta, nullptr, nullptr, b_dt);

    // ---- join: scan needs z16 ----------------------------------------------
    cudaStreamWaitEvent(0, evJoin, 0);
    scan_kernel<<<(ROWS * 8) / 128, 128>>>(delta, uc16, z16, Bm, Cm, A_log, Dp, y16);

    // ---- G5: out = y @ W_out (fp16 1-term, BM=64) --------------------------
    gemm_tc<EPI_PLAIN, 1><<<dim3(D_MODEL / GBN, ROWS / 64), 256, SM1>>>(
        (const uint8_t*)y16, (const uint8_t*)Wout16,
        D_INNER, D_INNER, D_INNER, D_MODEL,
        out, nullptr, nullptr, nullptr);
}